// round 1
// baseline (speedup 1.0000x reference)
#include <cuda_runtime.h>
#include <math.h>

#define N_POINTS   4194304
#define NUM_LEVELS 16
#define HASH_MASK  ((1u << 19) - 1u)
#define BLOCK      256

// Per-level (res-1) as float, computed on host with numpy-identical double math,
// passed by value (baked into the captured graph — capture-safe, no H2D copy).
struct ResParams { float rm1[NUM_LEVELS]; };

__global__ __launch_bounds__(BLOCK)
void hashenc_kernel(const float*  __restrict__ pts,
                    const float*  __restrict__ tables,
                    float*        __restrict__ out,
                    ResParams rp)
{
    const int n = blockIdx.x * BLOCK + threadIdx.x;

    // Coalesced within a warp: 32 lanes cover 384 contiguous bytes. Stream hint:
    // points are touched exactly once per replay.
    const float x = __ldcs(pts + 3 * (size_t)n + 0);
    const float y = __ldcs(pts + 3 * (size_t)n + 1);
    const float z = __ldcs(pts + 3 * (size_t)n + 2);

    // normalize [-1,1] -> [0,1], clamp (matches jnp.clip((p+1)*0.5, 0, 1))
    const float fx = fminf(fmaxf((x + 1.0f) * 0.5f, 0.0f), 1.0f);
    const float fy = fminf(fmaxf((y + 1.0f) * 0.5f, 0.0f), 1.0f);
    const float fz = fminf(fmaxf((z + 1.0f) * 0.5f, 0.0f), 1.0f);

    float2 feat[NUM_LEVELS];

    // 16 independent gathers -> MLP=16 hides L2/DRAM latency.
    #pragma unroll
    for (int l = 0; l < NUM_LEVELS; ++l) {
        const float rm1 = rp.rm1[l];
        // float->uint cast is cvt.rzi (truncate) == floor for non-negative values
        const unsigned cx = (unsigned)(fx * rm1);
        const unsigned cy = (unsigned)(fy * rm1);
        const unsigned cz = (unsigned)(fz * rm1);
        // h = c0*1 ^ c1*2654435761 ^ c2*805459861, uint32 wraparound, mod 2^19
        const unsigned h = (cx ^ (cy * 2654435761u) ^ (cz * 805459861u)) & HASH_MASK;
        const float2* tab = reinterpret_cast<const float2*>(tables)
                          + ((size_t)l << 19) + h;
        feat[l] = __ldg(tab);   // default caching: keep tables resident in L2
    }

    // 128B contiguous row per thread; 8x STG.128 with streaming (evict-first)
    // hint so the 512MB output stream does not evict the L2-resident tables.
    float4* o = reinterpret_cast<float4*>(out + (size_t)n * 32);
    #pragma unroll
    for (int i = 0; i < 8; ++i) {
        float4 v = make_float4(feat[2*i].x, feat[2*i].y,
                               feat[2*i+1].x, feat[2*i+1].y);
        __stcs(o + i, v);
    }
}

extern "C" void kernel_launch(void* const* d_in, const int* in_sizes, int n_in,
                              void* d_out, int out_size)
{
    (void)in_sizes; (void)n_in; (void)out_size;

    // Recompute resolutions with the SAME double-precision expression and
    // associativity as the numpy reference:
    //   int(floor(BASE_RES * exp(i * log(FINEST/BASE) / (L-1))))
    // where numpy evaluates (i * log(128.0)) / 15.0 left-to-right.
    ResParams rp;
    const double l128 = log(128.0);
    for (int i = 0; i < NUM_LEVELS; ++i) {
        const int res = (int)floor(16.0 * exp(((double)i * l128) / 15.0));
        rp.rm1[i] = (float)(res - 1);
    }

    const float* pts    = (const float*)d_in[0];
    const float* tables = (const float*)d_in[1];
    float*       out    = (float*)d_out;

    hashenc_kernel<<<N_POINTS / BLOCK, BLOCK>>>(pts, tables, out, rp);
}

// round 2
// speedup vs baseline: 1.0126x; 1.0126x over previous
#include <cuda_runtime.h>
#include <math.h>

#define N_POINTS   4194304
#define NUM_LEVELS 16
#define HASH_MASK  ((1u << 19) - 1u)
#define BLOCK      256

// Per-level (res-1) as float, computed on host with numpy-identical double math,
// passed by value (baked into the captured graph — capture-safe, no H2D copy).
struct ResParams { float rm1[NUM_LEVELS]; };

// Fine levels (>= this) bypass L1 (.cg): their 4MB tables can't be L1-resident
// and would only thrash the coarse levels' entries out of L1.
#define L1_CUTOFF 6

__global__ __launch_bounds__(BLOCK, 2)   // allow up to 128 regs: keep ALL 16 gathers in flight
void hashenc_kernel(const float*  __restrict__ pts,
                    const float*  __restrict__ tables,
                    float*        __restrict__ out,
                    ResParams rp)
{
    const int n = blockIdx.x * BLOCK + threadIdx.x;

    const float x = __ldcs(pts + 3 * (size_t)n + 0);
    const float y = __ldcs(pts + 3 * (size_t)n + 1);
    const float z = __ldcs(pts + 3 * (size_t)n + 2);

    // normalize [-1,1] -> [0,1], clamp (matches jnp.clip((p+1)*0.5, 0, 1))
    const float fx = fminf(fmaxf((x + 1.0f) * 0.5f, 0.0f), 1.0f);
    const float fy = fminf(fmaxf((y + 1.0f) * 0.5f, 0.0f), 1.0f);
    const float fz = fminf(fmaxf((z + 1.0f) * 0.5f, 0.0f), 1.0f);

    // Phase 1: compute all 16 table pointers (cheap ALU, frees addr regs early).
    const float2* p[NUM_LEVELS];
    #pragma unroll
    for (int l = 0; l < NUM_LEVELS; ++l) {
        const float rm1 = rp.rm1[l];
        // float->uint cast is cvt.rzi (truncate) == floor for non-negative values
        const unsigned cx = (unsigned)(fx * rm1);
        const unsigned cy = (unsigned)(fy * rm1);
        const unsigned cz = (unsigned)(fz * rm1);
        const unsigned h = (cx ^ (cy * 2654435761u) ^ (cz * 805459861u)) & HASH_MASK;
        p[l] = reinterpret_cast<const float2*>(tables) + ((size_t)l << 19) + h;
    }

    // Phase 2: issue all 16 independent gathers back-to-back (MLP=16).
    // Coarse levels keep L1 (.nc default); fine levels bypass L1 (.cg).
    float2 feat[NUM_LEVELS];
    #pragma unroll
    for (int l = 0; l < NUM_LEVELS; ++l) {
        if (l < L1_CUTOFF) feat[l] = __ldg(p[l]);
        else               feat[l] = __ldcg(p[l]);
    }

    // Phase 3: 128B contiguous row per thread, 8x STG.128 streaming (evict-first)
    // so the 512MB output stream doesn't evict L1/L2-resident table entries.
    float4* o = reinterpret_cast<float4*>(out + (size_t)n * 32);
    #pragma unroll
    for (int i = 0; i < 8; ++i) {
        float4 v = make_float4(feat[2*i].x, feat[2*i].y,
                               feat[2*i+1].x, feat[2*i+1].y);
        __stcs(o + i, v);
    }
}

extern "C" void kernel_launch(void* const* d_in, const int* in_sizes, int n_in,
                              void* d_out, int out_size)
{
    (void)in_sizes; (void)n_in; (void)out_size;

    // Recompute resolutions with the SAME double-precision expression and
    // associativity as the numpy reference.
    ResParams rp;
    const double l128 = log(128.0);
    for (int i = 0; i < NUM_LEVELS; ++i) {
        const int res = (int)floor(16.0 * exp(((double)i * l128) / 15.0));
        rp.rm1[i] = (float)(res - 1);
    }

    const float* pts    = (const float*)d_in[0];
    const float* tables = (const float*)d_in[1];
    float*       out    = (float*)d_out;

    hashenc_kernel<<<N_POINTS / BLOCK, BLOCK>>>(pts, tables, out, rp);
}